// round 11
// baseline (speedup 1.0000x reference)
#include <cuda_runtime.h>
#include <cuda_bf16.h>
#include <math.h>

#define NPIX     768
#define NP       (NPIX * NPIX)     // 589824 floats per basis term
#define NP4      (NP / 4)          // 147456 float4 per basis term
#define ROW4     (NPIX / 4)        // 192 float4 per row
#define NTERMS   128
#define PPSZ     256
#define THREADS  288               // 3 rows x 96 float4 = 288 float4 per region
#define HALFJ4   96                // 384 floats / 4
#define PF       8                 // prefetch pipeline depth (8 x float4 in flight)

// ---------------------------------------------------------------------------
// Fully fused, block-local kernel (R10 structure) with an explicit depth-8
// software-pipelined load loop. __launch_bounds__(288, 3) raises the register
// budget (~75) so ptxas can keep the whole 8 x float4 prefetch window live —
// at 32 regs (previous build) true MLP was ~4 and the stream ran at only
// 6.1 TB/s. Plain loads (NOT __ldcs: evict-first costs ~12% stream BW).
// ---------------------------------------------------------------------------
__global__ void __launch_bounds__(THREADS, 3) fused_climb_kernel(
    const float4* __restrict__ basis4,
    const float*  __restrict__ coeffs,
    const float*  __restrict__ wavel_ptr,
    float*        __restrict__ out)
{
    __shared__ float sc[NTERMS];
    __shared__ float tile[3][384];   // latent band: tile[c][localJ]

    int t = threadIdx.x;
    if (t < NTERMS) sc[t] = coeffs[t];
    __syncthreads();

    int Cb    = blockIdx.x >> 1;     // 0..255
    int Jhalf = blockIdx.x & 1;      // 0..1

    // This thread's float4 slot within the 3x384 region
    int row  = t / HALFJ4;           // 0..2  (c index / I-row within band)
    int col4 = t % HALFJ4;           // 0..95

    const float4* p = basis4
        + (size_t)(3 * Cb + row) * ROW4
        + (size_t)Jhalf * HALFJ4
        + col4;

    float4 acc0 = make_float4(0.f, 0.f, 0.f, 0.f);
    float4 acc1 = make_float4(0.f, 0.f, 0.f, 0.f);

    // ---- depth-8 software pipeline over the 128 terms ----
    float4 buf[PF];
#pragma unroll
    for (int i = 0; i < PF; i++)
        buf[i] = p[(size_t)i * NP4];

    for (int n = 0; n < NTERMS - PF; n += PF) {
        float4 nxt[PF];
#pragma unroll
        for (int i = 0; i < PF; i++)
            nxt[i] = p[(size_t)(n + PF + i) * NP4];

#pragma unroll
        for (int i = 0; i < PF; i++) {
            float c = sc[n + i];
            float4 v = buf[i];
            if (i & 1) {
                acc1.x = fmaf(v.x, c, acc1.x);
                acc1.y = fmaf(v.y, c, acc1.y);
                acc1.z = fmaf(v.z, c, acc1.z);
                acc1.w = fmaf(v.w, c, acc1.w);
            } else {
                acc0.x = fmaf(v.x, c, acc0.x);
                acc0.y = fmaf(v.y, c, acc0.y);
                acc0.z = fmaf(v.z, c, acc0.z);
                acc0.w = fmaf(v.w, c, acc0.w);
            }
        }
#pragma unroll
        for (int i = 0; i < PF; i++)
            buf[i] = nxt[i];
    }
    // drain last group
#pragma unroll
    for (int i = 0; i < PF; i++) {
        float c = sc[NTERMS - PF + i];
        float4 v = buf[i];
        if (i & 1) {
            acc1.x = fmaf(v.x, c, acc1.x);
            acc1.y = fmaf(v.y, c, acc1.y);
            acc1.z = fmaf(v.z, c, acc1.z);
            acc1.w = fmaf(v.w, c, acc1.w);
        } else {
            acc0.x = fmaf(v.x, c, acc0.x);
            acc0.y = fmaf(v.y, c, acc0.y);
            acc0.z = fmaf(v.z, c, acc0.z);
            acc0.w = fmaf(v.w, c, acc0.w);
        }
    }
    float4 acc = make_float4(acc0.x + acc1.x, acc0.y + acc1.y,
                             acc0.z + acc1.z, acc0.w + acc1.w);

    // Stage latent band in shared memory
    *reinterpret_cast<float4*>(&tile[row][col4 * 4]) = acc;
    __syncthreads();

    // ---- CLIMB patch compute: threads 0..127 each handle one patch ----
    if (t < 128) {
        int pch = t;                         // local patch index (J direction)
        // z[3r+c] = latent[I = 3Cb+c, J = Jbase + 3*pch + r] = tile[c][3*pch+r]
        float z[9];
#pragma unroll
        for (int c = 0; c < 3; c++) {
#pragma unroll
            for (int r = 0; r < 3; r++) {
                z[3 * r + c] = tile[c][3 * pch + r];
            }
        }

        // LSQ plane fit over unit 3x3 grid (orthogonal regressors):
        //   a = sum z*(x-1/2)/1.5,  b = sum z*(y-1/2)/1.5,
        //   cc = mean(z) - a/2 - b/2
        float S = 0.f, Sx = 0.f, Sy = 0.f;
        bool allpos = true, allnonpos = true, anyzero = false;
#pragma unroll
        for (int k = 0; k < 9; k++) {
            float v  = z[k];
            float xk = 0.5f * (float)(k % 3);
            float yk = 0.5f * (float)(k / 3);
            S  += v;
            Sx += v * xk;
            Sy += v * yk;
            allpos    = allpos    && (v > 0.f);
            allnonpos = allnonpos && (v <= 0.f);
            anyzero   = anyzero   || (v == 0.f);
        }
        float mean = S * (1.f / 9.f);
        float a  = (Sx - 0.5f * S) * (1.f / 1.5f);
        float b  = (Sy - 0.5f * S) * (1.f / 1.5f);
        float cc = mean - 0.5f * a - 0.5f * b;

        const float EPSF = 1e-15f;
        if (a  == 0.f) a  = EPSF;
        if (b  == 0.f) b  = EPSF;
        if (cc == 0.f) cc = EPSF;

        float x1 = (-b - cc) / a;
        float x2 = (-cc) / a;
        float lo = fminf(x1, x2);
        float hi = fmaxf(x1, x2);
        x1 = fmaxf(lo, 0.f);
        x2 = fminf(hi, 1.f);

        float ncb = (-cc) / b;
        float ab  = a / b;
        float d = x1 + ncb * x2 - 0.5f * ab * x2 * x2
                     - ncb * x1 + 0.5f * ab * x1 * x1;

        d = (d >= 0.5f)   ? d : (1.0f - d);
        d = (mean >= 0.f) ? d : (1.0f - d);
        if (allpos)    d = 1.0f;
        if (allnonpos) d = 0.0f;
        if (anyzero)   d = (d > 0.f) ? 1.0f : 0.0f;
        d = fminf(fmaxf(d, 0.f), 1.f);

        // opd = pi*d * wavel / (2*pi)
        float wl = *wavel_ptr;
        int Rb = Jhalf * 128 + pch;
        out[Cb * PPSZ + Rb] = ((float)M_PI * d) * wl * (1.0f / (2.0f * (float)M_PI));
    }
}

extern "C" void kernel_launch(void* const* d_in, const int* in_sizes, int n_in,
                              void* d_out, int out_size)
{
    const float4* basis4 = reinterpret_cast<const float4*>(d_in[0]); // (128,768,768) f32
    const float*  coeffs = reinterpret_cast<const float*>(d_in[1]);  // (128,)
    const float*  wavel  = reinterpret_cast<const float*>(d_in[2]);  // scalar
    float*        out    = reinterpret_cast<float*>(d_out);          // (256,256) f32

    (void)in_sizes; (void)n_in; (void)out_size;

    fused_climb_kernel<<<512, THREADS>>>(basis4, coeffs, wavel, out);
}

// round 12
// speedup vs baseline: 1.1320x; 1.1320x over previous
#include <cuda_runtime.h>
#include <cuda_bf16.h>
#include <math.h>

#define NPIX     768
#define NP       (NPIX * NPIX)     // 589824 floats per basis term
#define NP4      (NP / 4)          // 147456 float4 per basis term
#define ROW4     (NPIX / 4)        // 192 float4 per row
#define NTERMS   128
#define PPSZ     256
#define THREADS  288               // 3 rows x 96 float4-slots (x2 J-halves)
#define NBLOCKS  256               // one block per Cb patch-band

// ---------------------------------------------------------------------------
// Fully fused, block-local kernel. Each of 256 blocks owns one full Cb band:
// basis rows [3Cb, 3Cb+3), all 768 columns. Each thread owns TWO float4
// (same row, J-half 0 and 1) -> two naturally independent load streams per
// iteration, doubling in-flight bytes per SM vs the 1-load/thread version
// (which measured only 6.1 TB/s). Only ~2 blocks/SM resident -> >100 regs
// available, so the unroll-4 window (16 outstanding LDG.128) fits in
// registers with NO arrays and NO manual pipelining (R11's explicit buf[]
// pipeline spilled to local and collapsed to 4.5 TB/s).
// Epilogue: stage 3x768 latent band in smem, threads 0..255 compute the 256
// patches of the band. No global latent, no barrier, no second launch.
// ---------------------------------------------------------------------------
__global__ void __launch_bounds__(THREADS) fused_climb_kernel(
    const float4* __restrict__ basis4,
    const float*  __restrict__ coeffs,
    const float*  __restrict__ wavel_ptr,
    float*        __restrict__ out)
{
    __shared__ float sc[NTERMS];
    __shared__ float tile[3][NPIX];   // latent band: tile[c][J]  (9.2 KB)

    int t = threadIdx.x;
    if (t < NTERMS) sc[t] = coeffs[t];
    __syncthreads();

    int Cb   = blockIdx.x;           // 0..255
    int row  = t / 96;               // 0..2  (c index / I-row within band)
    int col4 = t % 96;               // 0..95 (float4 slot within J-half 0)

    const float4* p0 = basis4 + (size_t)(3 * Cb + row) * ROW4 + col4;
    const float4* p1 = p0 + 96;      // J-half 1, same row: independent stream

    float4 a0 = make_float4(0.f, 0.f, 0.f, 0.f);
    float4 a1 = make_float4(0.f, 0.f, 0.f, 0.f);

#pragma unroll 4
    for (int n = 0; n < NTERMS; n++) {
        float4 v0 = p0[(size_t)n * NP4];
        float4 v1 = p1[(size_t)n * NP4];
        float  c  = sc[n];
        a0.x = fmaf(v0.x, c, a0.x);
        a0.y = fmaf(v0.y, c, a0.y);
        a0.z = fmaf(v0.z, c, a0.z);
        a0.w = fmaf(v0.w, c, a0.w);
        a1.x = fmaf(v1.x, c, a1.x);
        a1.y = fmaf(v1.y, c, a1.y);
        a1.z = fmaf(v1.z, c, a1.z);
        a1.w = fmaf(v1.w, c, a1.w);
    }

    // Stage latent band in shared memory
    *reinterpret_cast<float4*>(&tile[row][col4 * 4])        = a0;
    *reinterpret_cast<float4*>(&tile[row][(col4 + 96) * 4]) = a1;
    __syncthreads();

    // ---- CLIMB patch compute: threads 0..255, one patch each ----
    if (t < 256) {
        int pch = t;                 // patch index along J (= Rb)
        // z[3r+c] = latent[I = 3Cb+c, J = 3*pch + r] = tile[c][3*pch + r]
        float z[9];
#pragma unroll
        for (int c = 0; c < 3; c++) {
#pragma unroll
            for (int r = 0; r < 3; r++) {
                z[3 * r + c] = tile[c][3 * pch + r];
            }
        }

        // LSQ plane fit over unit 3x3 grid (orthogonal regressors):
        //   a = sum z*(x-1/2)/1.5,  b = sum z*(y-1/2)/1.5,
        //   cc = mean(z) - a/2 - b/2
        float S = 0.f, Sx = 0.f, Sy = 0.f;
        bool allpos = true, allnonpos = true, anyzero = false;
#pragma unroll
        for (int k = 0; k < 9; k++) {
            float v  = z[k];
            float xk = 0.5f * (float)(k % 3);
            float yk = 0.5f * (float)(k / 3);
            S  += v;
            Sx += v * xk;
            Sy += v * yk;
            allpos    = allpos    && (v > 0.f);
            allnonpos = allnonpos && (v <= 0.f);
            anyzero   = anyzero   || (v == 0.f);
        }
        float mean = S * (1.f / 9.f);
        float a  = (Sx - 0.5f * S) * (1.f / 1.5f);
        float b  = (Sy - 0.5f * S) * (1.f / 1.5f);
        float cc = mean - 0.5f * a - 0.5f * b;

        const float EPSF = 1e-15f;
        if (a  == 0.f) a  = EPSF;
        if (b  == 0.f) b  = EPSF;
        if (cc == 0.f) cc = EPSF;

        float x1 = (-b - cc) / a;
        float x2 = (-cc) / a;
        float lo = fminf(x1, x2);
        float hi = fmaxf(x1, x2);
        x1 = fmaxf(lo, 0.f);
        x2 = fminf(hi, 1.f);

        float ncb = (-cc) / b;
        float ab  = a / b;
        float d = x1 + ncb * x2 - 0.5f * ab * x2 * x2
                     - ncb * x1 + 0.5f * ab * x1 * x1;

        d = (d >= 0.5f)   ? d : (1.0f - d);
        d = (mean >= 0.f) ? d : (1.0f - d);
        if (allpos)    d = 1.0f;
        if (allnonpos) d = 0.0f;
        if (anyzero)   d = (d > 0.f) ? 1.0f : 0.0f;
        d = fminf(fmaxf(d, 0.f), 1.f);

        // opd = pi*d * wavel / (2*pi)
        float wl = *wavel_ptr;
        out[Cb * PPSZ + pch] = ((float)M_PI * d) * wl * (1.0f / (2.0f * (float)M_PI));
    }
}

extern "C" void kernel_launch(void* const* d_in, const int* in_sizes, int n_in,
                              void* d_out, int out_size)
{
    const float4* basis4 = reinterpret_cast<const float4*>(d_in[0]); // (128,768,768) f32
    const float*  coeffs = reinterpret_cast<const float*>(d_in[1]);  // (128,)
    const float*  wavel  = reinterpret_cast<const float*>(d_in[2]);  // scalar
    float*        out    = reinterpret_cast<float*>(d_out);          // (256,256) f32

    (void)in_sizes; (void)n_in; (void)out_size;

    fused_climb_kernel<<<NBLOCKS, THREADS>>>(basis4, coeffs, wavel, out);
}

// round 13
// speedup vs baseline: 1.5979x; 1.4115x over previous
#include <cuda_runtime.h>
#include <cuda_bf16.h>
#include <math.h>

#define NPIX     768
#define NP       (NPIX * NPIX)     // 589824 floats per basis term
#define NP4      (NP / 4)          // 147456 float4 per basis term
#define ROW4     (NPIX / 4)        // 192 float4 per row
#define NTERMS   128
#define PPSZ     256
#define THREADS  288               // 3 rows x 96 float4 = 288 float4 per region
#define HALFJ4   96                // 384 floats / 4

// ---------------------------------------------------------------------------
// Fully fused, block-local kernel (R10 structure: 512 blocks, each owns a
// 3-row x 384-col patch-aligned band; epilogue from shared memory; no global
// latent, no grid barrier, no second launch).
//
// Streaming loop: EXPLICIT batch of 8 independent scalar float4 loads per
// iteration. No arrays (R11's buf[] pipeline spilled to local), no __ldcs
// (costs ~12% stream BW). __launch_bounds__(288, 4) caps regs at 56: enough
// for the 8-load window (evidence: the 46-reg build streamed ~6.6 TB/s,
// 32-reg builds only ~6.1), while 4 blocks/SM capacity keeps all 512 blocks
// co-resident (no waves).
// ---------------------------------------------------------------------------
__global__ void __launch_bounds__(THREADS, 4) fused_climb_kernel(
    const float4* __restrict__ basis4,
    const float*  __restrict__ coeffs,
    const float*  __restrict__ wavel_ptr,
    float*        __restrict__ out)
{
    __shared__ float sc[NTERMS];
    __shared__ float tile[3][384];   // latent band: tile[c][localJ]

    int t = threadIdx.x;
    if (t < NTERMS) sc[t] = coeffs[t];
    __syncthreads();

    int Cb    = blockIdx.x >> 1;     // 0..255
    int Jhalf = blockIdx.x & 1;      // 0..1

    int row  = t / HALFJ4;           // 0..2  (c index / I-row within band)
    int col4 = t % HALFJ4;           // 0..95

    const float4* p = basis4
        + (size_t)(3 * Cb + row) * ROW4
        + (size_t)Jhalf * HALFJ4
        + col4;

    float4 acc = make_float4(0.f, 0.f, 0.f, 0.f);

#pragma unroll 1
    for (int n = 0; n < NTERMS; n += 8) {
        // 8 independent scalar loads — the full window issues before any use.
        float4 v0 = p[(size_t)(n + 0) * NP4];
        float4 v1 = p[(size_t)(n + 1) * NP4];
        float4 v2 = p[(size_t)(n + 2) * NP4];
        float4 v3 = p[(size_t)(n + 3) * NP4];
        float4 v4 = p[(size_t)(n + 4) * NP4];
        float4 v5 = p[(size_t)(n + 5) * NP4];
        float4 v6 = p[(size_t)(n + 6) * NP4];
        float4 v7 = p[(size_t)(n + 7) * NP4];

        float c0 = sc[n + 0], c1 = sc[n + 1], c2 = sc[n + 2], c3 = sc[n + 3];
        float c4 = sc[n + 4], c5 = sc[n + 5], c6 = sc[n + 6], c7 = sc[n + 7];

        acc.x = fmaf(v0.x, c0, acc.x); acc.y = fmaf(v0.y, c0, acc.y);
        acc.z = fmaf(v0.z, c0, acc.z); acc.w = fmaf(v0.w, c0, acc.w);
        acc.x = fmaf(v1.x, c1, acc.x); acc.y = fmaf(v1.y, c1, acc.y);
        acc.z = fmaf(v1.z, c1, acc.z); acc.w = fmaf(v1.w, c1, acc.w);
        acc.x = fmaf(v2.x, c2, acc.x); acc.y = fmaf(v2.y, c2, acc.y);
        acc.z = fmaf(v2.z, c2, acc.z); acc.w = fmaf(v2.w, c2, acc.w);
        acc.x = fmaf(v3.x, c3, acc.x); acc.y = fmaf(v3.y, c3, acc.y);
        acc.z = fmaf(v3.z, c3, acc.z); acc.w = fmaf(v3.w, c3, acc.w);
        acc.x = fmaf(v4.x, c4, acc.x); acc.y = fmaf(v4.y, c4, acc.y);
        acc.z = fmaf(v4.z, c4, acc.z); acc.w = fmaf(v4.w, c4, acc.w);
        acc.x = fmaf(v5.x, c5, acc.x); acc.y = fmaf(v5.y, c5, acc.y);
        acc.z = fmaf(v5.z, c5, acc.z); acc.w = fmaf(v5.w, c5, acc.w);
        acc.x = fmaf(v6.x, c6, acc.x); acc.y = fmaf(v6.y, c6, acc.y);
        acc.z = fmaf(v6.z, c6, acc.z); acc.w = fmaf(v6.w, c6, acc.w);
        acc.x = fmaf(v7.x, c7, acc.x); acc.y = fmaf(v7.y, c7, acc.y);
        acc.z = fmaf(v7.z, c7, acc.z); acc.w = fmaf(v7.w, c7, acc.w);
    }

    // Stage latent band in shared memory
    *reinterpret_cast<float4*>(&tile[row][col4 * 4]) = acc;
    __syncthreads();

    // ---- CLIMB patch compute: threads 0..127 each handle one patch ----
    if (t < 128) {
        int pch = t;                         // local patch index (J direction)
        // z[3r+c] = latent[I = 3Cb+c, J = Jbase + 3*pch + r] = tile[c][3*pch+r]
        float z[9];
#pragma unroll
        for (int c = 0; c < 3; c++) {
#pragma unroll
            for (int r = 0; r < 3; r++) {
                z[3 * r + c] = tile[c][3 * pch + r];
            }
        }

        // LSQ plane fit over unit 3x3 grid (orthogonal regressors):
        //   a = sum z*(x-1/2)/1.5,  b = sum z*(y-1/2)/1.5,
        //   cc = mean(z) - a/2 - b/2
        float S = 0.f, Sx = 0.f, Sy = 0.f;
        bool allpos = true, allnonpos = true, anyzero = false;
#pragma unroll
        for (int k = 0; k < 9; k++) {
            float v  = z[k];
            float xk = 0.5f * (float)(k % 3);
            float yk = 0.5f * (float)(k / 3);
            S  += v;
            Sx += v * xk;
            Sy += v * yk;
            allpos    = allpos    && (v > 0.f);
            allnonpos = allnonpos && (v <= 0.f);
            anyzero   = anyzero   || (v == 0.f);
        }
        float mean = S * (1.f / 9.f);
        float a  = (Sx - 0.5f * S) * (1.f / 1.5f);
        float b  = (Sy - 0.5f * S) * (1.f / 1.5f);
        float cc = mean - 0.5f * a - 0.5f * b;

        const float EPSF = 1e-15f;
        if (a  == 0.f) a  = EPSF;
        if (b  == 0.f) b  = EPSF;
        if (cc == 0.f) cc = EPSF;

        float x1 = (-b - cc) / a;
        float x2 = (-cc) / a;
        float lo = fminf(x1, x2);
        float hi = fmaxf(x1, x2);
        x1 = fmaxf(lo, 0.f);
        x2 = fminf(hi, 1.f);

        float ncb = (-cc) / b;
        float ab  = a / b;
        float d = x1 + ncb * x2 - 0.5f * ab * x2 * x2
                     - ncb * x1 + 0.5f * ab * x1 * x1;

        d = (d >= 0.5f)   ? d : (1.0f - d);
        d = (mean >= 0.f) ? d : (1.0f - d);
        if (allpos)    d = 1.0f;
        if (allnonpos) d = 0.0f;
        if (anyzero)   d = (d > 0.f) ? 1.0f : 0.0f;
        d = fminf(fmaxf(d, 0.f), 1.f);

        // opd = pi*d * wavel / (2*pi)
        float wl = *wavel_ptr;
        int Rb = Jhalf * 128 + pch;
        out[Cb * PPSZ + Rb] = ((float)M_PI * d) * wl * (1.0f / (2.0f * (float)M_PI));
    }
}

extern "C" void kernel_launch(void* const* d_in, const int* in_sizes, int n_in,
                              void* d_out, int out_size)
{
    const float4* basis4 = reinterpret_cast<const float4*>(d_in[0]); // (128,768,768) f32
    const float*  coeffs = reinterpret_cast<const float*>(d_in[1]);  // (128,)
    const float*  wavel  = reinterpret_cast<const float*>(d_in[2]);  // scalar
    float*        out    = reinterpret_cast<float*>(d_out);          // (256,256) f32

    (void)in_sizes; (void)n_in; (void)out_size;

    fused_climb_kernel<<<512, THREADS>>>(basis4, coeffs, wavel, out);
}